// round 15
// baseline (speedup 1.0000x reference)
#include <cuda_runtime.h>
#include <cuda_bf16.h>
#include <math.h>
#include <stdint.h>
#include <stddef.h>

#define B_     4096
#define L_     32
#define FEAT_  128
#define H_     512
#define C_     256
#define FM_    64
#define G4H_   (4 * H_)

#define XS_STRIDE  ((size_t)B_ * L_ * FEAT_)
#define H1S_STRIDE ((size_t)B_ * L_ * H_)
#define HS_STRIDE  ((size_t)B_ * H_)

// ---------------- scratch ----------------
__device__ float g_gates[(size_t)B_ * G4H_];
__device__ float g_h[(size_t)B_ * H_];
__device__ float g_c[(size_t)B_ * H_];
__device__ float g_bias0[G4H_];
__device__ float g_bias1[G4H_];
__device__ float g_immm[(size_t)B_ * FM_];
__device__ float g_t1[(size_t)B_ * H_];
__device__ float g_t2[(size_t)B_ * H_];
__device__ float g_cat[(size_t)B_ * 2 * C_];
__device__ float g_fused[(size_t)B_ * 2 * C_];
__device__ __nv_bfloat16 g_xs[3 * XS_STRIDE];
__device__ __nv_bfloat16 g_h1s[3 * H1S_STRIDE];
__device__ __nv_bfloat16 g_hs[3 * HS_STRIDE];
__device__ __nv_bfloat16 g_Wi0[3 * (size_t)G4H_ * FEAT_];
__device__ __nv_bfloat16 g_Wh0[3 * (size_t)G4H_ * H_];
__device__ __nv_bfloat16 g_Wi1[3 * (size_t)G4H_ * H_];
__device__ __nv_bfloat16 g_Wh1[3 * (size_t)G4H_ * H_];

// ---------------- helpers ----------------
__device__ __forceinline__ uint32_t smem_u32(const void* p) {
    uint32_t a;
    asm("{ .reg .u64 t; cvta.to.shared.u64 t, %1; cvt.u32.u64 %0, t; }" : "=r"(a) : "l"(p));
    return a;
}
__device__ __forceinline__ void cp16(uint32_t dst, const void* src) {
    asm volatile("cp.async.cg.shared.global [%0], [%1], 16;" :: "r"(dst), "l"(src) : "memory");
}

// ---------------- recurrent bf16-split GEMM via mma.sync ----------------
// gates[4096,2048] = sum over 8 split segments of [x|h] @ [Wih|Whh]^T
struct GemmArgs {
    const __nv_bfloat16* A0[3];
    const __nv_bfloat16* A1[3];
    const __nv_bfloat16* B0[3];
    const __nv_bfloat16* B1[3];
    int sA0, sA1, sB0, sB1;
    float* Cout;
};
// segment split-level tables: la={0,0,1,1,0,2,1,2}, lb={0,1,0,1,2,0,2,1}
#define LA_PACK 0x9850
#define LB_PACK 0x6244

// SMEM tile: 128 rows x 32 bf16 (64B data) padded to 80B row stride
// (80B stride => 8-row groups hit 8 distinct bank quads for ldmatrix).
#define TROW 80

template<int TPS, int P0T>
__device__ __forceinline__ void load_tile(const GemmArgs& a, int kt,
                                          uint32_t smA, uint32_t smB,
                                          int rowA, int colB, int tid)
{
    const int seg = kt / TPS;
    int it = kt - seg * TPS;
    const int la = (LA_PACK >> (seg * 2)) & 3;
    const int lb = (LB_PACK >> (seg * 2)) & 3;
    const __nv_bfloat16 *Ap, *Bp; int sA, sB;
    if (it < P0T) {
        Ap = a.A0[la] + it * 32; sA = a.sA0;
        Bp = a.B0[lb] + it * 32; sB = a.sB0;
    } else {
        it -= P0T;
        Ap = a.A1[la] + it * 32; sA = a.sA1;
        Bp = a.B1[lb] + it * 32; sB = a.sB1;
    }
#pragma unroll
    for (int i = 0; i < 2; i++) {       // A: 128 rows x 4 x 16B chunks
        const int q = i * 256 + tid, r = q >> 2, c = q & 3;
        cp16(smA + r * TROW + c * 16, Ap + (size_t)(rowA + r) * sA + c * 8);
    }
#pragma unroll
    for (int i = 0; i < 2; i++) {       // B
        const int q = i * 256 + tid, r = q >> 2, c = q & 3;
        cp16(smB + r * TROW + c * 16, Bp + (size_t)(colB + r) * sB + c * 8);
    }
    asm volatile("cp.async.commit_group;" ::: "memory");
}

template<int TPS, int P0T, int NT>
__global__ __launch_bounds__(256, 2)
void lstm_gemm(GemmArgs a)
{
    __shared__ __align__(128) char sm[4 * 128 * TROW];   // A0,B0,A1,B1
    const uint32_t smb = smem_u32(sm);
    const uint32_t AB[2] = {smb,                 smb + 2u * 128 * TROW};
    const uint32_t BB[2] = {smb + 1u * 128 * TROW, smb + 3u * 128 * TROW};

    const int tid = threadIdx.x, wid = tid >> 5, lane = tid & 31;
    const int wm = wid & 1;        // 2 warps over M (64 rows each)
    const int wn = wid >> 1;       // 4 warps over N (32 cols each)
    const int rowA = blockIdx.y * 128, colB = blockIdx.x * 128;

    float acc[4][4][4];
#pragma unroll
    for (int i = 0; i < 4; i++)
#pragma unroll
        for (int j = 0; j < 4; j++)
#pragma unroll
            for (int k = 0; k < 4; k++) acc[i][j][k] = 0.f;

    load_tile<TPS, P0T>(a, 0, AB[0], BB[0], rowA, colB, tid);
    load_tile<TPS, P0T>(a, 1, AB[1], BB[1], rowA, colB, tid);

    for (int kt = 0; kt < NT; kt++) {
        const int buf = kt & 1;
        if (kt + 1 < NT) asm volatile("cp.async.wait_group 1;" ::: "memory");
        else             asm volatile("cp.async.wait_group 0;" ::: "memory");
        __syncthreads();

#pragma unroll
        for (int k16 = 0; k16 < 2; k16++) {
            uint32_t af[4][4], bf[4][2];
#pragma unroll
            for (int mf = 0; mf < 4; mf++) {
                const uint32_t ad = AB[buf]
                    + (uint32_t)(wm * 64 + mf * 16 + (lane & 15)) * TROW
                    + (uint32_t)(k16 * 16 + (lane >> 4) * 8) * 2u;
                asm volatile("ldmatrix.sync.aligned.m8n8.x4.shared.b16 {%0,%1,%2,%3}, [%4];"
                    : "=r"(af[mf][0]), "=r"(af[mf][1]), "=r"(af[mf][2]), "=r"(af[mf][3])
                    : "r"(ad));
            }
#pragma unroll
            for (int np = 0; np < 2; np++) {
                const uint32_t bd = BB[buf]
                    + (uint32_t)(wn * 32 + np * 16 + (lane >> 4) * 8 + (lane & 7)) * TROW
                    + (uint32_t)(k16 * 16 + ((lane >> 3) & 1) * 8) * 2u;
                uint32_t r0, r1, r2, r3;
                asm volatile("ldmatrix.sync.aligned.m8n8.x4.shared.b16 {%0,%1,%2,%3}, [%4];"
                    : "=r"(r0), "=r"(r1), "=r"(r2), "=r"(r3) : "r"(bd));
                bf[np * 2][0] = r0; bf[np * 2][1] = r1;
                bf[np * 2 + 1][0] = r2; bf[np * 2 + 1][1] = r3;
            }
#pragma unroll
            for (int mf = 0; mf < 4; mf++)
#pragma unroll
                for (int nf = 0; nf < 4; nf++)
                    asm volatile("mma.sync.aligned.m16n8k16.row.col.f32.bf16.bf16.f32 "
                        "{%0,%1,%2,%3}, {%4,%5,%6,%7}, {%8,%9}, {%0,%1,%2,%3};"
                        : "+f"(acc[mf][nf][0]), "+f"(acc[mf][nf][1]),
                          "+f"(acc[mf][nf][2]), "+f"(acc[mf][nf][3])
                        : "r"(af[mf][0]), "r"(af[mf][1]), "r"(af[mf][2]), "r"(af[mf][3]),
                          "r"(bf[nf][0]), "r"(bf[nf][1]));
        }
        __syncthreads();
        if (kt + 2 < NT)
            load_tile<TPS, P0T>(a, kt + 2, AB[buf], BB[buf], rowA, colB, tid);
    }

    // epilogue: acc(mf,nf): rows lane/4 (+8), cols (lane%4)*2 (+1)
#pragma unroll
    for (int mf = 0; mf < 4; mf++) {
        const int r = rowA + wm * 64 + mf * 16 + (lane >> 2);
#pragma unroll
        for (int nf = 0; nf < 4; nf++) {
            const int c = colB + wn * 32 + nf * 8 + (lane & 3) * 2;
            float* p0 = a.Cout + (size_t)r * G4H_ + c;
            float* p1 = p0 + (size_t)8 * G4H_;
            p0[0] = acc[mf][nf][0]; p0[1] = acc[mf][nf][1];
            p1[0] = acc[mf][nf][2]; p1[1] = acc[mf][nf][3];
        }
    }
}

// ---------------- split / elementwise ----------------
__device__ __forceinline__ void split3(float a, __nv_bfloat16& b0, __nv_bfloat16& b1, __nv_bfloat16& b2) {
    b0 = __float2bfloat16(a);
    float r = a - __bfloat162float(b0);
    b1 = __float2bfloat16(r);
    b2 = __float2bfloat16(r - __bfloat162float(b1));
}
__global__ void split_x_kernel(const float* __restrict__ x) {
    size_t i = (size_t)blockIdx.x * blockDim.x + threadIdx.x;
    if (i >= XS_STRIDE) return;
    __nv_bfloat16 b0, b1, b2;
    split3(x[i], b0, b1, b2);
    g_xs[i] = b0; g_xs[XS_STRIDE + i] = b1; g_xs[2 * XS_STRIDE + i] = b2;
}
__global__ void split_w_kernel(const float* __restrict__ src, __nv_bfloat16* __restrict__ dst,
                               size_t lvlStride, int n) {
    int i = blockIdx.x * blockDim.x + threadIdx.x;
    if (i >= n) return;
    __nv_bfloat16 b0, b1, b2;
    split3(src[i], b0, b1, b2);
    dst[i] = b0; dst[lvlStride + i] = b1; dst[2 * lvlStride + i] = b2;
}
__global__ void prep_bias_kernel(const float* __restrict__ bih0, const float* __restrict__ bhh0,
                                 const float* __restrict__ bih1, const float* __restrict__ bhh1) {
    int i = blockIdx.x * blockDim.x + threadIdx.x;
    if (i < G4H_) { g_bias0[i] = bih0[i] + bhh0[i]; g_bias1[i] = bih1[i] + bhh1[i]; }
}
__global__ void zero_state_kernel() {
    int i = blockIdx.x * blockDim.x + threadIdx.x;
    if (i >= B_ * H_) return;
    g_c[i] = 0.f;
    __nv_bfloat16 z = __float2bfloat16(0.f);
    g_hs[i] = z; g_hs[HS_STRIDE + i] = z; g_hs[2 * HS_STRIDE + i] = z;
}
__device__ __forceinline__ float dsigmoid(float x) { return 1.f / (1.f + expf(-x)); }

__global__ void lstm_cell2_kernel(int t, int layer, const float* __restrict__ bias) {
    int idx = blockIdx.x * blockDim.x + threadIdx.x;
    if (idx >= B_ * H_) return;
    const int b = idx >> 9, j = idx & 511;
    const float* gr = g_gates + (size_t)b * G4H_;
    const float ig = dsigmoid(gr[j] + bias[j]);
    const float fg = dsigmoid(gr[H_ + j] + bias[H_ + j]);
    const float gg = tanhf(gr[2 * H_ + j] + bias[2 * H_ + j]);
    const float og = dsigmoid(gr[3 * H_ + j] + bias[3 * H_ + j]);
    const float cn = fg * g_c[idx] + ig * gg;
    const float hn = og * tanhf(cn);
    g_c[idx] = cn;
    __nv_bfloat16 b0, b1, b2;
    split3(hn, b0, b1, b2);
    g_hs[idx] = b0; g_hs[HS_STRIDE + idx] = b1; g_hs[2 * HS_STRIDE + idx] = b2;
    if (layer == 0) {
        const size_t o = ((size_t)b * L_ + t) * H_ + j;
        g_h1s[o] = b0; g_h1s[H1S_STRIDE + o] = b1; g_h1s[2 * H1S_STRIDE + o] = b2;
    } else {
        g_h[idx] = hn;
    }
}

// ---------------- fp32 SGEMM (tails; proven) ----------------
#define BM 128
#define BN 128
#define BK 8
#define TM 8
#define TN 8
__global__ __launch_bounds__(256, 2)
void sgemm_dual(const float* __restrict__ A1, int lda1,
                const float* __restrict__ B1, int ldb1,
                const float* __restrict__ bias,
                const float* __restrict__ aux, int ldaux,
                float* __restrict__ C, int ldc, int K, int epi)
{
    __shared__ __align__(16) float As[2][BK][BM + 4];
    __shared__ __align__(16) float Bs[2][BK][BN + 4];
    const int tid = threadIdx.x, tx = tid & 15, ty = tid >> 4;
    const int rowBase = blockIdx.y * BM, colBase = blockIdx.x * BN;
    const int lr = tid >> 1, lk = (tid & 1) * 4;
    float acc[TM][TN];
#pragma unroll
    for (int i = 0; i < TM; i++)
#pragma unroll
        for (int j = 0; j < TN; j++) acc[i][j] = 0.f;
    const int ntiles = K / BK;
    {
        float4 av = *(const float4*)(A1 + (size_t)(rowBase + lr) * lda1 + lk);
        float4 bv = *(const float4*)(B1 + (size_t)(colBase + lr) * ldb1 + lk);
        As[0][lk + 0][lr] = av.x; As[0][lk + 1][lr] = av.y;
        As[0][lk + 2][lr] = av.z; As[0][lk + 3][lr] = av.w;
        Bs[0][lk + 0][lr] = bv.x; Bs[0][lk + 1][lr] = bv.y;
        Bs[0][lk + 2][lr] = bv.z; Bs[0][lk + 3][lr] = bv.w;
    }
    __syncthreads();
    for (int kt = 0; kt < ntiles; kt++) {
        const int buf = kt & 1;
        float4 av2, bv2;
        const bool hasNext = (kt + 1 < ntiles);
        if (hasNext) {
            const int k0 = (kt + 1) * BK;
            av2 = *(const float4*)(A1 + (size_t)(rowBase + lr) * lda1 + k0 + lk);
            bv2 = *(const float4*)(B1 + (size_t)(colBase + lr) * ldb1 + k0 + lk);
        }
#pragma unroll
        for (int kk = 0; kk < BK; kk++) {
            float4 a0 = *(const float4*)&As[buf][kk][ty * TM];
            float4 a1 = *(const float4*)&As[buf][kk][ty * TM + 4];
            float4 b0 = *(const float4*)&Bs[buf][kk][tx * TN];
            float4 b1 = *(const float4*)&Bs[buf][kk][tx * TN + 4];
            float a[TM] = {a0.x, a0.y, a0.z, a0.w, a1.x, a1.y, a1.z, a1.w};
            float b[TN] = {b0.x, b0.y, b0.z, b0.w, b1.x, b1.y, b1.z, b1.w};
#pragma unroll
            for (int i = 0; i < TM; i++)
#pragma unroll
                for (int j = 0; j < TN; j++)
                    acc[i][j] = fmaf(a[i], b[j], acc[i][j]);
        }
        if (hasNext) {
            const int nb = buf ^ 1;
            As[nb][lk + 0][lr] = av2.x; As[nb][lk + 1][lr] = av2.y;
            As[nb][lk + 2][lr] = av2.z; As[nb][lk + 3][lr] = av2.w;
            Bs[nb][lk + 0][lr] = bv2.x; Bs[nb][lk + 1][lr] = bv2.y;
            Bs[nb][lk + 2][lr] = bv2.z; Bs[nb][lk + 3][lr] = bv2.w;
            __syncthreads();
        }
    }
#pragma unroll
    for (int i = 0; i < TM; i++) {
        const int r = rowBase + ty * TM + i;
#pragma unroll
        for (int j = 0; j < TN; j++) {
            const int cidx = colBase + tx * TN + j;
            float v = acc[i][j] + bias[cidx];
            if (epi == 1) v = v > 0.f ? v : 0.f;
            else if (epi == 2) v = aux[(size_t)r * ldaux + cidx] * (1.f / (1.f + expf(-v)));
            C[(size_t)r * ldc + cidx] = v;
        }
    }
}

__global__ void topk_mask_kernel(const float* __restrict__ out_sub, const float* __restrict__ y)
{
    const int warp = (blockIdx.x * blockDim.x + threadIdx.x) >> 5;
    const int lane = threadIdx.x & 31;
    if (warp >= B_) return;
    const float* row = out_sub + (size_t)warp * C_;
    float p = 0.f;
#pragma unroll
    for (int k = 0; k < 8; k++) p += row[lane * 8 + k];
    unsigned selmask = 0;
    float v = p;
#pragma unroll
    for (int it = 0; it < 8; it++) {
        float m = v; int mi = lane;
#pragma unroll
        for (int off = 16; off; off >>= 1) {
            const float ov = __shfl_xor_sync(0xffffffffu, m, off);
            const int   oi = __shfl_xor_sync(0xffffffffu, mi, off);
            if (ov > m || (ov == m && oi < mi)) { m = ov; mi = oi; }
        }
        selmask |= 1u << mi;
        if (lane == mi) v = -INFINITY;
    }
    const float sel = ((selmask >> lane) & 1u) ? 1.f : 0.f;
    const size_t base = (size_t)warp * FM_ + 2 * lane;
    g_immm[base]     = y[base]     * sel;
    g_immm[base + 1] = y[base + 1] * sel;
}

__global__ void cat_kernel(const float* __restrict__ out_sub, const float* __restrict__ out_mm)
{
    int idx = blockIdx.x * blockDim.x + threadIdx.x;
    if (idx >= B_ * 2 * C_) return;
    const int b = idx >> 9, j = idx & 511;
    g_cat[idx] = (j < C_) ? out_sub[(size_t)b * C_ + j] : out_mm[(size_t)b * C_ + (j - C_)];
}

// ---------------- host ----------------
static inline void gemm32(const float* A, int lda, const float* Bw, int ldb,
                          const float* bias, const float* aux, int ldaux,
                          float* C, int ldc, int M, int N, int K, int epi)
{
    dim3 grid(N / BN, M / BM);
    sgemm_dual<<<grid, 256>>>(A, lda, Bw, ldb, bias, aux, ldaux, C, ldc, K, epi);
}

extern "C" void kernel_launch(void* const* d_in, const int* in_sizes, int n_in,
                              void* d_out, int out_size)
{
    const float* x    = (const float*)d_in[0];
    const float* y    = (const float*)d_in[1];
    const float* Wih0 = (const float*)d_in[2];
    const float* Whh0 = (const float*)d_in[3];
    const float* bih0 = (const float*)d_in[4];
    const float* bhh0 = (const float*)d_in[5];
    const float* Wih1 = (const float*)d_in[6];
    const float* Whh1 = (const float*)d_in[7];
    const float* bih1 = (const float*)d_in[8];
    const float* bhh1 = (const float*)d_in[9];
    const float* decW = (const float*)d_in[10];
    const float* decb = (const float*)d_in[11];
    const float* mmW1 = (const float*)d_in[12];
    const float* mmb1 = (const float*)d_in[13];
    const float* mmW2 = (const float*)d_in[14];
    const float* mmb2 = (const float*)d_in[15];
    const float* mmW3 = (const float*)d_in[16];
    const float* mmb3 = (const float*)d_in[17];
    const float* attW = (const float*)d_in[18];
    const float* attb = (const float*)d_in[19];
    const float* fuW1 = (const float*)d_in[20];
    const float* fub1 = (const float*)d_in[21];
    const float* fuW2 = (const float*)d_in[22];
    const float* fub2 = (const float*)d_in[23];
    const float* fuW3 = (const float*)d_in[24];
    const float* fub3 = (const float*)d_in[25];
    (void)in_sizes; (void)n_in; (void)out_size;

    float* out     = (float*)d_out;
    float* out_sub = out;
    float* out_mm  = out + (size_t)B_ * C_;
    float* out_fu  = out + (size_t)2 * B_ * C_;

    float *gates, *h, *bs0, *bs1, *immm, *t1, *t2, *cat, *fused;
    __nv_bfloat16 *xs, *h1s, *hs, *wi0, *wh0, *wi1, *wh1;
    cudaGetSymbolAddress((void**)&gates, g_gates);
    cudaGetSymbolAddress((void**)&h,     g_h);
    cudaGetSymbolAddress((void**)&bs0,   g_bias0);
    cudaGetSymbolAddress((void**)&bs1,   g_bias1);
    cudaGetSymbolAddress((void**)&immm,  g_immm);
    cudaGetSymbolAddress((void**)&t1,    g_t1);
    cudaGetSymbolAddress((void**)&t2,    g_t2);
    cudaGetSymbolAddress((void**)&cat,   g_cat);
    cudaGetSymbolAddress((void**)&fused, g_fused);
    cudaGetSymbolAddress((void**)&xs,    g_xs);
    cudaGetSymbolAddress((void**)&h1s,   g_h1s);
    cudaGetSymbolAddress((void**)&hs,    g_hs);
    cudaGetSymbolAddress((void**)&wi0,   g_Wi0);
    cudaGetSymbolAddress((void**)&wh0,   g_Wh0);
    cudaGetSymbolAddress((void**)&wi1,   g_Wi1);
    cudaGetSymbolAddress((void**)&wh1,   g_Wh1);

    const int hcBlocks = (B_ * H_ + 255) / 256;
    prep_bias_kernel<<<(G4H_ + 255) / 256, 256>>>(bih0, bhh0, bih1, bhh1);
    split_x_kernel<<<(int)(XS_STRIDE / 256), 256>>>(x);
    split_w_kernel<<<(G4H_ * FEAT_ + 255) / 256, 256>>>(Wih0, wi0, (size_t)G4H_ * FEAT_, G4H_ * FEAT_);
    split_w_kernel<<<(G4H_ * H_ + 255) / 256, 256>>>(Whh0, wh0, (size_t)G4H_ * H_, G4H_ * H_);
    split_w_kernel<<<(G4H_ * H_ + 255) / 256, 256>>>(Wih1, wi1, (size_t)G4H_ * H_, G4H_ * H_);
    split_w_kernel<<<(G4H_ * H_ + 255) / 256, 256>>>(Whh1, wh1, (size_t)G4H_ * H_, G4H_ * H_);

    dim3 ggrid(G4H_ / 128, B_ / 128);   // (16, 32)

    // ---- layer 0: seg K = FEAT+H = 640 -> 20 tiles (4 x-part), 8 segs = 160 ----
    zero_state_kernel<<<hcBlocks, 256>>>();
    {
        GemmArgs a;
        a.sA0 = L_ * FEAT_; a.sA1 = H_; a.sB0 = FEAT_; a.sB1 = H_;
        a.Cout = gates;
        for (int l = 0; l < 3; l++) {
            a.A1[l] = hs + (size_t)l * HS_STRIDE;
            a.B0[l] = wi0 + (size_t)l * G4H_ * FEAT_;
            a.B1[l] = wh0 + (size_t)l * G4H_ * H_;
        }
        for (int t = 0; t < L_; t++) {
            for (int l = 0; l < 3; l++) a.A0[l] = xs + (size_t)l * XS_STRIDE + (size_t)t * FEAT_;
            lstm_gemm<20, 4, 160><<<ggrid, 256>>>(a);
            lstm_cell2_kernel<<<hcBlocks, 256>>>(t, 0, bs0);
        }
    }
    // ---- layer 1: seg K = 2H = 1024 -> 32 tiles (16 h1-part), 8 segs = 256 ----
    zero_state_kernel<<<hcBlocks, 256>>>();
    {
        GemmArgs a;
        a.sA0 = L_ * H_; a.sA1 = H_; a.sB0 = H_; a.sB1 = H_;
        a.Cout = gates;
        for (int l = 0; l < 3; l++) {
            a.A1[l] = hs + (size_t)l * HS_STRIDE;
            a.B0[l] = wi1 + (size_t)l * G4H_ * H_;
            a.B1[l] = wh1 + (size_t)l * G4H_ * H_;
        }
        for (int t = 0; t < L_; t++) {
            for (int l = 0; l < 3; l++) a.A0[l] = h1s + (size_t)l * H1S_STRIDE + (size_t)t * H_;
            lstm_gemm<32, 16, 256><<<ggrid, 256>>>(a);
            lstm_cell2_kernel<<<hcBlocks, 256>>>(t, 1, bs1);
        }
    }

    // ---- tails (fp32, proven) ----
    gemm32(h, H_, decW, H_, decb, nullptr, 0, out_sub, C_, B_, C_, H_, 0);
    topk_mask_kernel<<<(B_ * 32 + 255) / 256, 256>>>(out_sub, y);
    gemm32(immm, FM_, mmW1, FM_, mmb1, nullptr, 0, t1, H_, B_, H_, FM_, 1);
    gemm32(t1, H_, mmW2, H_, mmb2, nullptr, 0, t2, H_, B_, H_, H_, 1);
    gemm32(t2, H_, mmW3, H_, mmb3, nullptr, 0, out_mm, C_, B_, C_, H_, 0);
    cat_kernel<<<(B_ * 2 * C_ + 255) / 256, 256>>>(out_sub, out_mm);
    gemm32(cat, 2 * C_, attW, 2 * C_, attb, cat, 2 * C_, fused, 2 * C_, B_, 2 * C_, 2 * C_, 2);
    gemm32(fused, 2 * C_, fuW1, 2 * C_, fub1, nullptr, 0, t1, H_, B_, H_, 2 * C_, 1);
    gemm32(t1, H_, fuW2, H_, fub2, nullptr, 0, t2, H_, B_, H_, H_, 1);
    gemm32(t2, H_, fuW3, H_, fub3, nullptr, 0, out_fu, C_, B_, C_, H_, 0);
}

// round 16
// speedup vs baseline: 1.0011x; 1.0011x over previous
#include <cuda_runtime.h>
#include <cuda_bf16.h>
#include <math.h>
#include <stdint.h>
#include <stddef.h>

#define B_     4096
#define L_     32
#define FEAT_  128
#define H_     512
#define C_     256
#define FM_    64
#define G4H_   (4 * H_)

#define XS_STRIDE  ((size_t)B_ * L_ * FEAT_)
#define H1S_STRIDE ((size_t)B_ * L_ * H_)
#define HS_STRIDE  ((size_t)B_ * H_)

// ---------------- scratch ----------------
__device__ float g_gates[(size_t)B_ * G4H_];
__device__ float g_h[(size_t)B_ * H_];
__device__ float g_c[(size_t)B_ * H_];
__device__ float g_bias0[G4H_];
__device__ float g_bias1[G4H_];
__device__ float g_immm[(size_t)B_ * FM_];
__device__ float g_t1[(size_t)B_ * H_];
__device__ float g_t2[(size_t)B_ * H_];
__device__ float g_cat[(size_t)B_ * 2 * C_];
__device__ float g_fused[(size_t)B_ * 2 * C_];
__device__ __nv_bfloat16 g_xs[3 * XS_STRIDE];
__device__ __nv_bfloat16 g_h1s[3 * H1S_STRIDE];
__device__ __nv_bfloat16 g_hs[3 * HS_STRIDE];
__device__ __nv_bfloat16 g_Wi0[3 * (size_t)G4H_ * FEAT_];
__device__ __nv_bfloat16 g_Wh0[3 * (size_t)G4H_ * H_];
__device__ __nv_bfloat16 g_Wi1[3 * (size_t)G4H_ * H_];
__device__ __nv_bfloat16 g_Wh1[3 * (size_t)G4H_ * H_];

// ---------------- helpers ----------------
__device__ __forceinline__ uint32_t smem_u32(const void* p) {
    uint32_t a;
    asm("{ .reg .u64 t; cvta.to.shared.u64 t, %1; cvt.u32.u64 %0, t; }" : "=r"(a) : "l"(p));
    return a;
}
__device__ __forceinline__ void cp16(uint32_t dst, const void* src) {
    asm volatile("cp.async.cg.shared.global [%0], [%1], 16;" :: "r"(dst), "l"(src) : "memory");
}

// ---------------- recurrent bf16-split GEMM via mma.sync ----------------
// gates[4096,2048] = sum over 8 split segments of [x|h] @ [Wih|Whh]^T
struct GemmArgs {
    const __nv_bfloat16* A0[3];
    const __nv_bfloat16* A1[3];
    const __nv_bfloat16* B0[3];
    const __nv_bfloat16* B1[3];
    int sA0, sA1, sB0, sB1;
    float* Cout;
};
// segment split-level tables: la={0,0,1,1,0,2,1,2}, lb={0,1,0,1,2,0,2,1}
#define LA_PACK 0x9850
#define LB_PACK 0x6244

// SMEM tile: 128 rows x 32 bf16 (64B data) padded to 80B row stride
// (80B stride => 8-row groups hit 8 distinct bank quads for ldmatrix).
#define TROW 80

template<int TPS, int P0T>
__device__ __forceinline__ void load_tile(const GemmArgs& a, int kt,
                                          uint32_t smA, uint32_t smB,
                                          int rowA, int colB, int tid)
{
    const int seg = kt / TPS;
    int it = kt - seg * TPS;
    const int la = (LA_PACK >> (seg * 2)) & 3;
    const int lb = (LB_PACK >> (seg * 2)) & 3;
    const __nv_bfloat16 *Ap, *Bp; int sA, sB;
    if (it < P0T) {
        Ap = a.A0[la] + it * 32; sA = a.sA0;
        Bp = a.B0[lb] + it * 32; sB = a.sB0;
    } else {
        it -= P0T;
        Ap = a.A1[la] + it * 32; sA = a.sA1;
        Bp = a.B1[lb] + it * 32; sB = a.sB1;
    }
#pragma unroll
    for (int i = 0; i < 2; i++) {       // A: 128 rows x 4 x 16B chunks
        const int q = i * 256 + tid, r = q >> 2, c = q & 3;
        cp16(smA + r * TROW + c * 16, Ap + (size_t)(rowA + r) * sA + c * 8);
    }
#pragma unroll
    for (int i = 0; i < 2; i++) {       // B
        const int q = i * 256 + tid, r = q >> 2, c = q & 3;
        cp16(smB + r * TROW + c * 16, Bp + (size_t)(colB + r) * sB + c * 8);
    }
    asm volatile("cp.async.commit_group;" ::: "memory");
}

template<int TPS, int P0T, int NT>
__global__ __launch_bounds__(256, 2)
void lstm_gemm(GemmArgs a)
{
    __shared__ __align__(128) char sm[4 * 128 * TROW];   // A0,B0,A1,B1
    const uint32_t smb = smem_u32(sm);
    const uint32_t AB[2] = {smb,                 smb + 2u * 128 * TROW};
    const uint32_t BB[2] = {smb + 1u * 128 * TROW, smb + 3u * 128 * TROW};

    const int tid = threadIdx.x, wid = tid >> 5, lane = tid & 31;
    const int wm = wid & 1;        // 2 warps over M (64 rows each)
    const int wn = wid >> 1;       // 4 warps over N (32 cols each)
    const int rowA = blockIdx.y * 128, colB = blockIdx.x * 128;

    float acc[4][4][4];
#pragma unroll
    for (int i = 0; i < 4; i++)
#pragma unroll
        for (int j = 0; j < 4; j++)
#pragma unroll
            for (int k = 0; k < 4; k++) acc[i][j][k] = 0.f;

    load_tile<TPS, P0T>(a, 0, AB[0], BB[0], rowA, colB, tid);
    load_tile<TPS, P0T>(a, 1, AB[1], BB[1], rowA, colB, tid);

    for (int kt = 0; kt < NT; kt++) {
        const int buf = kt & 1;
        if (kt + 1 < NT) asm volatile("cp.async.wait_group 1;" ::: "memory");
        else             asm volatile("cp.async.wait_group 0;" ::: "memory");
        __syncthreads();

#pragma unroll
        for (int k16 = 0; k16 < 2; k16++) {
            uint32_t af[4][4], bf[4][2];
#pragma unroll
            for (int mf = 0; mf < 4; mf++) {
                const uint32_t ad = AB[buf]
                    + (uint32_t)(wm * 64 + mf * 16 + (lane & 15)) * TROW
                    + (uint32_t)(k16 * 16 + (lane >> 4) * 8) * 2u;
                asm volatile("ldmatrix.sync.aligned.m8n8.x4.shared.b16 {%0,%1,%2,%3}, [%4];"
                    : "=r"(af[mf][0]), "=r"(af[mf][1]), "=r"(af[mf][2]), "=r"(af[mf][3])
                    : "r"(ad));
            }
#pragma unroll
            for (int np = 0; np < 2; np++) {
                const uint32_t bd = BB[buf]
                    + (uint32_t)(wn * 32 + np * 16 + (lane >> 4) * 8 + (lane & 7)) * TROW
                    + (uint32_t)(k16 * 16 + ((lane >> 3) & 1) * 8) * 2u;
                uint32_t r0, r1, r2, r3;
                asm volatile("ldmatrix.sync.aligned.m8n8.x4.shared.b16 {%0,%1,%2,%3}, [%4];"
                    : "=r"(r0), "=r"(r1), "=r"(r2), "=r"(r3) : "r"(bd));
                bf[np * 2][0] = r0; bf[np * 2][1] = r1;
                bf[np * 2 + 1][0] = r2; bf[np * 2 + 1][1] = r3;
            }
#pragma unroll
            for (int mf = 0; mf < 4; mf++)
#pragma unroll
                for (int nf = 0; nf < 4; nf++)
                    asm volatile("mma.sync.aligned.m16n8k16.row.col.f32.bf16.bf16.f32 "
                        "{%0,%1,%2,%3}, {%4,%5,%6,%7}, {%8,%9}, {%0,%1,%2,%3};"
                        : "+f"(acc[mf][nf][0]), "+f"(acc[mf][nf][1]),
                          "+f"(acc[mf][nf][2]), "+f"(acc[mf][nf][3])
                        : "r"(af[mf][0]), "r"(af[mf][1]), "r"(af[mf][2]), "r"(af[mf][3]),
                          "r"(bf[nf][0]), "r"(bf[nf][1]));
        }
        __syncthreads();
        if (kt + 2 < NT)
            load_tile<TPS, P0T>(a, kt + 2, AB[buf], BB[buf], rowA, colB, tid);
    }

    // epilogue: acc(mf,nf): rows lane/4 (+8), cols (lane%4)*2 (+1)
#pragma unroll
    for (int mf = 0; mf < 4; mf++) {
        const int r = rowA + wm * 64 + mf * 16 + (lane >> 2);
#pragma unroll
        for (int nf = 0; nf < 4; nf++) {
            const int c = colB + wn * 32 + nf * 8 + (lane & 3) * 2;
            float* p0 = a.Cout + (size_t)r * G4H_ + c;
            float* p1 = p0 + (size_t)8 * G4H_;
            p0[0] = acc[mf][nf][0]; p0[1] = acc[mf][nf][1];
            p1[0] = acc[mf][nf][2]; p1[1] = acc[mf][nf][3];
        }
    }
}

// ---------------- split / elementwise ----------------
__device__ __forceinline__ void split3(float a, __nv_bfloat16& b0, __nv_bfloat16& b1, __nv_bfloat16& b2) {
    b0 = __float2bfloat16(a);
    float r = a - __bfloat162float(b0);
    b1 = __float2bfloat16(r);
    b2 = __float2bfloat16(r - __bfloat162float(b1));
}
__global__ void split_x_kernel(const float* __restrict__ x) {
    size_t i = (size_t)blockIdx.x * blockDim.x + threadIdx.x;
    if (i >= XS_STRIDE) return;
    __nv_bfloat16 b0, b1, b2;
    split3(x[i], b0, b1, b2);
    g_xs[i] = b0; g_xs[XS_STRIDE + i] = b1; g_xs[2 * XS_STRIDE + i] = b2;
}
__global__ void split_w_kernel(const float* __restrict__ src, __nv_bfloat16* __restrict__ dst,
                               size_t lvlStride, int n) {
    int i = blockIdx.x * blockDim.x + threadIdx.x;
    if (i >= n) return;
    __nv_bfloat16 b0, b1, b2;
    split3(src[i], b0, b1, b2);
    dst[i] = b0; dst[lvlStride + i] = b1; dst[2 * lvlStride + i] = b2;
}
__global__ void prep_bias_kernel(const float* __restrict__ bih0, const float* __restrict__ bhh0,
                                 const float* __restrict__ bih1, const float* __restrict__ bhh1) {
    int i = blockIdx.x * blockDim.x + threadIdx.x;
    if (i < G4H_) { g_bias0[i] = bih0[i] + bhh0[i]; g_bias1[i] = bih1[i] + bhh1[i]; }
}
__global__ void zero_state_kernel() {
    int i = blockIdx.x * blockDim.x + threadIdx.x;
    if (i >= B_ * H_) return;
    g_c[i] = 0.f;
    __nv_bfloat16 z = __float2bfloat16(0.f);
    g_hs[i] = z; g_hs[HS_STRIDE + i] = z; g_hs[2 * HS_STRIDE + i] = z;
}
__device__ __forceinline__ float dsigmoid(float x) { return 1.f / (1.f + expf(-x)); }

__global__ void lstm_cell2_kernel(int t, int layer, const float* __restrict__ bias) {
    int idx = blockIdx.x * blockDim.x + threadIdx.x;
    if (idx >= B_ * H_) return;
    const int b = idx >> 9, j = idx & 511;
    const float* gr = g_gates + (size_t)b * G4H_;
    const float ig = dsigmoid(gr[j] + bias[j]);
    const float fg = dsigmoid(gr[H_ + j] + bias[H_ + j]);
    const float gg = tanhf(gr[2 * H_ + j] + bias[2 * H_ + j]);
    const float og = dsigmoid(gr[3 * H_ + j] + bias[3 * H_ + j]);
    const float cn = fg * g_c[idx] + ig * gg;
    const float hn = og * tanhf(cn);
    g_c[idx] = cn;
    __nv_bfloat16 b0, b1, b2;
    split3(hn, b0, b1, b2);
    g_hs[idx] = b0; g_hs[HS_STRIDE + idx] = b1; g_hs[2 * HS_STRIDE + idx] = b2;
    if (layer == 0) {
        const size_t o = ((size_t)b * L_ + t) * H_ + j;
        g_h1s[o] = b0; g_h1s[H1S_STRIDE + o] = b1; g_h1s[2 * H1S_STRIDE + o] = b2;
    } else {
        g_h[idx] = hn;
    }
}

// ---------------- fp32 SGEMM (tails; proven) ----------------
#define BM 128
#define BN 128
#define BK 8
#define TM 8
#define TN 8
__global__ __launch_bounds__(256, 2)
void sgemm_dual(const float* __restrict__ A1, int lda1,
                const float* __restrict__ B1, int ldb1,
                const float* __restrict__ bias,
                const float* __restrict__ aux, int ldaux,
                float* __restrict__ C, int ldc, int K, int epi)
{
    __shared__ __align__(16) float As[2][BK][BM + 4];
    __shared__ __align__(16) float Bs[2][BK][BN + 4];
    const int tid = threadIdx.x, tx = tid & 15, ty = tid >> 4;
    const int rowBase = blockIdx.y * BM, colBase = blockIdx.x * BN;
    const int lr = tid >> 1, lk = (tid & 1) * 4;
    float acc[TM][TN];
#pragma unroll
    for (int i = 0; i < TM; i++)
#pragma unroll
        for (int j = 0; j < TN; j++) acc[i][j] = 0.f;
    const int ntiles = K / BK;
    {
        float4 av = *(const float4*)(A1 + (size_t)(rowBase + lr) * lda1 + lk);
        float4 bv = *(const float4*)(B1 + (size_t)(colBase + lr) * ldb1 + lk);
        As[0][lk + 0][lr] = av.x; As[0][lk + 1][lr] = av.y;
        As[0][lk + 2][lr] = av.z; As[0][lk + 3][lr] = av.w;
        Bs[0][lk + 0][lr] = bv.x; Bs[0][lk + 1][lr] = bv.y;
        Bs[0][lk + 2][lr] = bv.z; Bs[0][lk + 3][lr] = bv.w;
    }
    __syncthreads();
    for (int kt = 0; kt < ntiles; kt++) {
        const int buf = kt & 1;
        float4 av2, bv2;
        const bool hasNext = (kt + 1 < ntiles);
        if (hasNext) {
            const int k0 = (kt + 1) * BK;
            av2 = *(const float4*)(A1 + (size_t)(rowBase + lr) * lda1 + k0 + lk);
            bv2 = *(const float4*)(B1 + (size_t)(colBase + lr) * ldb1 + k0 + lk);
        }
#pragma unroll
        for (int kk = 0; kk < BK; kk++) {
            float4 a0 = *(const float4*)&As[buf][kk][ty * TM];
            float4 a1 = *(const float4*)&As[buf][kk][ty * TM + 4];
            float4 b0 = *(const float4*)&Bs[buf][kk][tx * TN];
            float4 b1 = *(const float4*)&Bs[buf][kk][tx * TN + 4];
            float a[TM] = {a0.x, a0.y, a0.z, a0.w, a1.x, a1.y, a1.z, a1.w};
            float b[TN] = {b0.x, b0.y, b0.z, b0.w, b1.x, b1.y, b1.z, b1.w};
#pragma unroll
            for (int i = 0; i < TM; i++)
#pragma unroll
                for (int j = 0; j < TN; j++)
                    acc[i][j] = fmaf(a[i], b[j], acc[i][j]);
        }
        if (hasNext) {
            const int nb = buf ^ 1;
            As[nb][lk + 0][lr] = av2.x; As[nb][lk + 1][lr] = av2.y;
            As[nb][lk + 2][lr] = av2.z; As[nb][lk + 3][lr] = av2.w;
            Bs[nb][lk + 0][lr] = bv2.x; Bs[nb][lk + 1][lr] = bv2.y;
            Bs[nb][lk + 2][lr] = bv2.z; Bs[nb][lk + 3][lr] = bv2.w;
            __syncthreads();
        }
    }
#pragma unroll
    for (int i = 0; i < TM; i++) {
        const int r = rowBase + ty * TM + i;
#pragma unroll
        for (int j = 0; j < TN; j++) {
            const int cidx = colBase + tx * TN + j;
            float v = acc[i][j] + bias[cidx];
            if (epi == 1) v = v > 0.f ? v : 0.f;
            else if (epi == 2) v = aux[(size_t)r * ldaux + cidx] * (1.f / (1.f + expf(-v)));
            C[(size_t)r * ldc + cidx] = v;
        }
    }
}

__global__ void topk_mask_kernel(const float* __restrict__ out_sub, const float* __restrict__ y)
{
    const int warp = (blockIdx.x * blockDim.x + threadIdx.x) >> 5;
    const int lane = threadIdx.x & 31;
    if (warp >= B_) return;
    const float* row = out_sub + (size_t)warp * C_;
    float p = 0.f;
#pragma unroll
    for (int k = 0; k < 8; k++) p += row[lane * 8 + k];
    unsigned selmask = 0;
    float v = p;
#pragma unroll
    for (int it = 0; it < 8; it++) {
        float m = v; int mi = lane;
#pragma unroll
        for (int off = 16; off; off >>= 1) {
            const float ov = __shfl_xor_sync(0xffffffffu, m, off);
            const int   oi = __shfl_xor_sync(0xffffffffu, mi, off);
            if (ov > m || (ov == m && oi < mi)) { m = ov; mi = oi; }
        }
        selmask |= 1u << mi;
        if (lane == mi) v = -INFINITY;
    }
    const float sel = ((selmask >> lane) & 1u) ? 1.f : 0.f;
    const size_t base = (size_t)warp * FM_ + 2 * lane;
    g_immm[base]     = y[base]     * sel;
    g_immm[base + 1] = y[base + 1] * sel;
}

__global__ void cat_kernel(const float* __restrict__ out_sub, const float* __restrict__ out_mm)
{
    int idx = blockIdx.x * blockDim.x + threadIdx.x;
    if (idx >= B_ * 2 * C_) return;
    const int b = idx >> 9, j = idx & 511;
    g_cat[idx] = (j < C_) ? out_sub[(size_t)b * C_ + j] : out_mm[(size_t)b * C_ + (j - C_)];
}

// ---------------- host ----------------
static inline void gemm32(const float* A, int lda, const float* Bw, int ldb,
                          const float* bias, const float* aux, int ldaux,
                          float* C, int ldc, int M, int N, int K, int epi)
{
    dim3 grid(N / BN, M / BM);
    sgemm_dual<<<grid, 256>>>(A, lda, Bw, ldb, bias, aux, ldaux, C, ldc, K, epi);
}

extern "C" void kernel_launch(void* const* d_in, const int* in_sizes, int n_in,
                              void* d_out, int out_size)
{
    const float* x    = (const float*)d_in[0];
    const float* y    = (const float*)d_in[1];
    const float* Wih0 = (const float*)d_in[2];
    const float* Whh0 = (const float*)d_in[3];
    const float* bih0 = (const float*)d_in[4];
    const float* bhh0 = (const float*)d_in[5];
    const float* Wih1 = (const float*)d_in[6];
    const float* Whh1 = (const float*)d_in[7];
    const float* bih1 = (const float*)d_in[8];
    const float* bhh1 = (const float*)d_in[9];
    const float* decW = (const float*)d_in[10];
    const float* decb = (const float*)d_in[11];
    const float* mmW1 = (const float*)d_in[12];
    const float* mmb1 = (const float*)d_in[13];
    const float* mmW2 = (const float*)d_in[14];
    const float* mmb2 = (const float*)d_in[15];
    const float* mmW3 = (const float*)d_in[16];
    const float* mmb3 = (const float*)d_in[17];
    const float* attW = (const float*)d_in[18];
    const float* attb = (const float*)d_in[19];
    const float* fuW1 = (const float*)d_in[20];
    const float* fub1 = (const float*)d_in[21];
    const float* fuW2 = (const float*)d_in[22];
    const float* fub2 = (const float*)d_in[23];
    const float* fuW3 = (const float*)d_in[24];
    const float* fub3 = (const float*)d_in[25];
    (void)in_sizes; (void)n_in; (void)out_size;

    float* out     = (float*)d_out;
    float* out_sub = out;
    float* out_mm  = out + (size_t)B_ * C_;
    float* out_fu  = out + (size_t)2 * B_ * C_;

    float *gates, *h, *bs0, *bs1, *immm, *t1, *t2, *cat, *fused;
    __nv_bfloat16 *xs, *h1s, *hs, *wi0, *wh0, *wi1, *wh1;
    cudaGetSymbolAddress((void**)&gates, g_gates);
    cudaGetSymbolAddress((void**)&h,     g_h);
    cudaGetSymbolAddress((void**)&bs0,   g_bias0);
    cudaGetSymbolAddress((void**)&bs1,   g_bias1);
    cudaGetSymbolAddress((void**)&immm,  g_immm);
    cudaGetSymbolAddress((void**)&t1,    g_t1);
    cudaGetSymbolAddress((void**)&t2,    g_t2);
    cudaGetSymbolAddress((void**)&cat,   g_cat);
    cudaGetSymbolAddress((void**)&fused, g_fused);
    cudaGetSymbolAddress((void**)&xs,    g_xs);
    cudaGetSymbolAddress((void**)&h1s,   g_h1s);
    cudaGetSymbolAddress((void**)&hs,    g_hs);
    cudaGetSymbolAddress((void**)&wi0,   g_Wi0);
    cudaGetSymbolAddress((void**)&wh0,   g_Wh0);
    cudaGetSymbolAddress((void**)&wi1,   g_Wi1);
    cudaGetSymbolAddress((void**)&wh1,   g_Wh1);

    const int hcBlocks = (B_ * H_ + 255) / 256;
    prep_bias_kernel<<<(G4H_ + 255) / 256, 256>>>(bih0, bhh0, bih1, bhh1);
    split_x_kernel<<<(int)(XS_STRIDE / 256), 256>>>(x);
    split_w_kernel<<<(G4H_ * FEAT_ + 255) / 256, 256>>>(Wih0, wi0, (size_t)G4H_ * FEAT_, G4H_ * FEAT_);
    split_w_kernel<<<(G4H_ * H_ + 255) / 256, 256>>>(Whh0, wh0, (size_t)G4H_ * H_, G4H_ * H_);
    split_w_kernel<<<(G4H_ * H_ + 255) / 256, 256>>>(Wih1, wi1, (size_t)G4H_ * H_, G4H_ * H_);
    split_w_kernel<<<(G4H_ * H_ + 255) / 256, 256>>>(Whh1, wh1, (size_t)G4H_ * H_, G4H_ * H_);

    dim3 ggrid(G4H_ / 128, B_ / 128);   // (16, 32)

    // ---- layer 0: seg K = FEAT+H = 640 -> 20 tiles (4 x-part), 8 segs = 160 ----
    zero_state_kernel<<<hcBlocks, 256>>>();
    {
        GemmArgs a;
        a.sA0 = L_ * FEAT_; a.sA1 = H_; a.sB0 = FEAT_; a.sB1 = H_;
        a.Cout = gates;
        for (int l = 0; l < 3; l++) {
            a.A1[l] = hs + (size_t)l * HS_STRIDE;
            a.B0[l] = wi0 + (size_t)l * G4H_ * FEAT_;
            a.B1[l] = wh0 + (size_t)l * G4H_ * H_;
        }
        for (int t = 0; t < L_; t++) {
            for (int l = 0; l < 3; l++) a.A0[l] = xs + (size_t)l * XS_STRIDE + (size_t)t * FEAT_;
            lstm_gemm<20, 4, 160><<<ggrid, 256>>>(a);
            lstm_cell2_kernel<<<hcBlocks, 256>>>(t, 0, bs0);
        }
    }
    // ---- layer 1: seg K = 2H = 1024 -> 32 tiles (16 h1-part), 8 segs = 256 ----
    zero_state_kernel<<<hcBlocks, 256>>>();
    {
        GemmArgs a;
        a.sA0 = L_ * H_; a.sA1 = H_; a.sB0 = H_; a.sB1 = H_;
        a.Cout = gates;
        for (int l = 0; l < 3; l++) {
            a.A1[l] = hs + (size_t)l * HS_STRIDE;
            a.B0[l] = wi1 + (size_t)l * G4H_ * H_;
            a.B1[l] = wh1 + (size_t)l * G4H_ * H_;
        }
        for (int t = 0; t < L_; t++) {
            for (int l = 0; l < 3; l++) a.A0[l] = h1s + (size_t)l * H1S_STRIDE + (size_t)t * H_;
            lstm_gemm<32, 16, 256><<<ggrid, 256>>>(a);
            lstm_cell2_kernel<<<hcBlocks, 256>>>(t, 1, bs1);
        }
    }

    // ---- tails (fp32, proven) ----
    gemm32(h, H_, decW, H_, decb, nullptr, 0, out_sub, C_, B_, C_, H_, 0);
    topk_mask_kernel<<<(B_ * 32 + 255) / 256, 256>>>(out_sub, y);
    gemm32(immm, FM_, mmW1, FM_, mmb1, nullptr, 0, t1, H_, B_, H_, FM_, 1);
    gemm32(t1, H_, mmW2, H_, mmb2, nullptr, 0, t2, H_, B_, H_, H_, 1);
    gemm32(t2, H_, mmW3, H_, mmb3, nullptr, 0, out_mm, C_, B_, C_, H_, 0);
    cat_kernel<<<(B_ * 2 * C_ + 255) / 256, 256>>>(out_sub, out_mm);
    gemm32(cat, 2 * C_, attW, 2 * C_, attb, cat, 2 * C_, fused, 2 * C_, B_, 2 * C_, 2 * C_, 2);
    gemm32(fused, 2 * C_, fuW1, 2 * C_, fub1, nullptr, 0, t1, H_, B_, H_, 2 * C_, 1);
    gemm32(t1, H_, fuW2, H_, fub2, nullptr, 0, t2, H_, B_, H_, H_, 1);
    gemm32(t2, H_, fuW3, H_, fub3, nullptr, 0, out_fu, C_, B_, C_, H_, 0);
}

// round 17
// speedup vs baseline: 2.5283x; 2.5254x over previous
#include <cuda_runtime.h>
#include <cuda_bf16.h>
#include <math.h>
#include <stdint.h>
#include <stddef.h>

#define B_     4096
#define L_     32
#define FEAT_  128
#define H_     512
#define C_     256
#define FM_    64
#define G4H_   (4 * H_)

#define XS_STRIDE  ((size_t)B_ * L_ * FEAT_)
#define H1S_STRIDE ((size_t)B_ * L_ * H_)
#define HS_STRIDE  ((size_t)B_ * H_)

// ---------------- scratch ----------------
__device__ float g_gates[(size_t)B_ * G4H_];
__device__ float g_xp0[(size_t)B_ * L_ * G4H_];   // layer0 input projection (1.07 GB)
__device__ float g_xp1[(size_t)B_ * L_ * G4H_];   // layer1 input projection (1.07 GB)
__device__ float g_h[(size_t)B_ * H_];
__device__ float g_c[(size_t)B_ * H_];
__device__ float g_bias0[G4H_];
__device__ float g_bias1[G4H_];
__device__ float g_immm[(size_t)B_ * FM_];
__device__ float g_t1[(size_t)B_ * H_];
__device__ float g_t2[(size_t)B_ * H_];
__device__ float g_cat[(size_t)B_ * 2 * C_];
__device__ float g_fused[(size_t)B_ * 2 * C_];
__device__ __nv_bfloat16 g_xs[2 * XS_STRIDE];
__device__ __nv_bfloat16 g_h1s[2 * H1S_STRIDE];
__device__ __nv_bfloat16 g_hs[2 * HS_STRIDE];
__device__ __nv_bfloat16 g_Wi0[2 * (size_t)G4H_ * FEAT_];
__device__ __nv_bfloat16 g_Wh0[2 * (size_t)G4H_ * H_];
__device__ __nv_bfloat16 g_Wi1[2 * (size_t)G4H_ * H_];
__device__ __nv_bfloat16 g_Wh1[2 * (size_t)G4H_ * H_];

// ---------------- helpers ----------------
__device__ __forceinline__ uint32_t smem_u32(const void* p) {
    uint32_t a;
    asm("{ .reg .u64 t; cvta.to.shared.u64 t, %1; cvt.u32.u64 %0, t; }" : "=r"(a) : "l"(p));
    return a;
}
__device__ __forceinline__ void cp16(uint32_t dst, const void* src) {
    asm volatile("cp.async.cg.shared.global [%0], [%1], 16;" :: "r"(dst), "l"(src) : "memory");
}

// ---------------- bf16-split GEMM via mma.sync ----------------
// C[M,2048] = sum over 3 split segments: (a0,b0),(a0,b1),(a1,b0)
struct GemmArgs {
    const __nv_bfloat16* A0[2];
    const __nv_bfloat16* A1[2];
    const __nv_bfloat16* B0[2];
    const __nv_bfloat16* B1[2];
    int sA0, sA1, sB0, sB1;
    float* Cout;
};
// seg level tables: la={0,0,1}, lb={0,1,0} (2 bits/seg)
#define LA_PACK 0x10
#define LB_PACK 0x04

#define TROW 80   // 128 rows x 32 bf16 padded to 80B stride (ldmatrix conflict-free)

template<int TPS, int P0T>
__device__ __forceinline__ void load_tile(const GemmArgs& a, int kt,
                                          uint32_t smA, uint32_t smB,
                                          int rowA, int colB, int tid)
{
    const int seg = kt / TPS;
    int it = kt - seg * TPS;
    const int la = (LA_PACK >> (seg * 2)) & 3;
    const int lb = (LB_PACK >> (seg * 2)) & 3;
    const __nv_bfloat16 *Ap, *Bp; int sA, sB;
    if (P0T > 0 && it < P0T) {
        Ap = a.A0[la] + it * 32; sA = a.sA0;
        Bp = a.B0[lb] + it * 32; sB = a.sB0;
    } else {
        it -= P0T;
        Ap = a.A1[la] + it * 32; sA = a.sA1;
        Bp = a.B1[lb] + it * 32; sB = a.sB1;
    }
#pragma unroll
    for (int i = 0; i < 2; i++) {
        const int q = i * 256 + tid, r = q >> 2, c = q & 3;
        cp16(smA + r * TROW + c * 16, Ap + (size_t)(rowA + r) * sA + c * 8);
    }
#pragma unroll
    for (int i = 0; i < 2; i++) {
        const int q = i * 256 + tid, r = q >> 2, c = q & 3;
        cp16(smB + r * TROW + c * 16, Bp + (size_t)(colB + r) * sB + c * 8);
    }
    asm volatile("cp.async.commit_group;" ::: "memory");
}

template<int TPS, int P0T, int NT>
__global__ __launch_bounds__(256, 2)
void lstm_gemm(GemmArgs a)
{
    __shared__ __align__(128) char sm[4 * 128 * TROW];
    const uint32_t smb = smem_u32(sm);
    const uint32_t AB[2] = {smb,                   smb + 2u * 128 * TROW};
    const uint32_t BB[2] = {smb + 1u * 128 * TROW, smb + 3u * 128 * TROW};

    const int tid = threadIdx.x, wid = tid >> 5, lane = tid & 31;
    const int wm = wid & 1;
    const int wn = wid >> 1;
    const int rowA = blockIdx.y * 128, colB = blockIdx.x * 128;

    float acc[4][4][4];
#pragma unroll
    for (int i = 0; i < 4; i++)
#pragma unroll
        for (int j = 0; j < 4; j++)
#pragma unroll
            for (int k = 0; k < 4; k++) acc[i][j][k] = 0.f;

    load_tile<TPS, P0T>(a, 0, AB[0], BB[0], rowA, colB, tid);
    load_tile<TPS, P0T>(a, 1, AB[1], BB[1], rowA, colB, tid);

    for (int kt = 0; kt < NT; kt++) {
        const int buf = kt & 1;
        if (kt + 1 < NT) asm volatile("cp.async.wait_group 1;" ::: "memory");
        else             asm volatile("cp.async.wait_group 0;" ::: "memory");
        __syncthreads();

#pragma unroll
        for (int k16 = 0; k16 < 2; k16++) {
            uint32_t af[4][4], bf[4][2];
#pragma unroll
            for (int mf = 0; mf < 4; mf++) {
                const uint32_t ad = AB[buf]
                    + (uint32_t)(wm * 64 + mf * 16 + (lane & 15)) * TROW
                    + (uint32_t)(k16 * 16 + (lane >> 4) * 8) * 2u;
                asm volatile("ldmatrix.sync.aligned.m8n8.x4.shared.b16 {%0,%1,%2,%3}, [%4];"
                    : "=r"(af[mf][0]), "=r"(af[mf][1]), "=r"(af[mf][2]), "=r"(af[mf][3])
                    : "r"(ad));
            }
#pragma unroll
            for (int np = 0; np < 2; np++) {
                const uint32_t bd = BB[buf]
                    + (uint32_t)(wn * 32 + np * 16 + (lane >> 4) * 8 + (lane & 7)) * TROW
                    + (uint32_t)(k16 * 16 + ((lane >> 3) & 1) * 8) * 2u;
                uint32_t r0, r1, r2, r3;
                asm volatile("ldmatrix.sync.aligned.m8n8.x4.shared.b16 {%0,%1,%2,%3}, [%4];"
                    : "=r"(r0), "=r"(r1), "=r"(r2), "=r"(r3) : "r"(bd));
                bf[np * 2][0] = r0; bf[np * 2][1] = r1;
                bf[np * 2 + 1][0] = r2; bf[np * 2 + 1][1] = r3;
            }
#pragma unroll
            for (int mf = 0; mf < 4; mf++)
#pragma unroll
                for (int nf = 0; nf < 4; nf++)
                    asm volatile("mma.sync.aligned.m16n8k16.row.col.f32.bf16.bf16.f32 "
                        "{%0,%1,%2,%3}, {%4,%5,%6,%7}, {%8,%9}, {%0,%1,%2,%3};"
                        : "+f"(acc[mf][nf][0]), "+f"(acc[mf][nf][1]),
                          "+f"(acc[mf][nf][2]), "+f"(acc[mf][nf][3])
                        : "r"(af[mf][0]), "r"(af[mf][1]), "r"(af[mf][2]), "r"(af[mf][3]),
                          "r"(bf[nf][0]), "r"(bf[nf][1]));
        }
        __syncthreads();
        if (kt + 2 < NT)
            load_tile<TPS, P0T>(a, kt + 2, AB[buf], BB[buf], rowA, colB, tid);
    }

#pragma unroll
    for (int mf = 0; mf < 4; mf++) {
        const int r = rowA + wm * 64 + mf * 16 + (lane >> 2);
#pragma unroll
        for (int nf = 0; nf < 4; nf++) {
            const int c = colB + wn * 32 + nf * 8 + (lane & 3) * 2;
            float* p0 = a.Cout + (size_t)r * G4H_ + c;
            float* p1 = p0 + (size_t)8 * G4H_;
            p0[0] = acc[mf][nf][0]; p0[1] = acc[mf][nf][1];
            p1[0] = acc[mf][nf][2]; p1[1] = acc[mf][nf][3];
        }
    }
}

// ---------------- split / elementwise ----------------
__device__ __forceinline__ void split2(float a, __nv_bfloat16& b0, __nv_bfloat16& b1) {
    b0 = __float2bfloat16(a);
    b1 = __float2bfloat16(a - __bfloat162float(b0));
}
__global__ void split_x_kernel(const float* __restrict__ x) {
    size_t i = (size_t)blockIdx.x * blockDim.x + threadIdx.x;
    if (i >= XS_STRIDE) return;
    __nv_bfloat16 b0, b1;
    split2(x[i], b0, b1);
    g_xs[i] = b0; g_xs[XS_STRIDE + i] = b1;
}
__global__ void split_w_kernel(const float* __restrict__ src, __nv_bfloat16* __restrict__ dst,
                               size_t lvlStride, int n) {
    int i = blockIdx.x * blockDim.x + threadIdx.x;
    if (i >= n) return;
    __nv_bfloat16 b0, b1;
    split2(src[i], b0, b1);
    dst[i] = b0; dst[lvlStride + i] = b1;
}
__global__ void prep_bias_kernel(const float* __restrict__ bih0, const float* __restrict__ bhh0,
                                 const float* __restrict__ bih1, const float* __restrict__ bhh1) {
    int i = blockIdx.x * blockDim.x + threadIdx.x;
    if (i < G4H_) { g_bias0[i] = bih0[i] + bhh0[i]; g_bias1[i] = bih1[i] + bhh1[i]; }
}
__global__ void zero_state_kernel() {
    int i = blockIdx.x * blockDim.x + threadIdx.x;
    if (i >= B_ * H_) return;
    g_c[i] = 0.f;
    __nv_bfloat16 z = __float2bfloat16(0.f);
    g_hs[i] = z; g_hs[HS_STRIDE + i] = z;
}
__device__ __forceinline__ float dsigmoid(float x) { return 1.f / (1.f + expf(-x)); }

// gates_total = (useGates ? g_gates : 0) + xp[b*L+t] + bias
__global__ void lstm_cell2_kernel(int t, int layer, const float* __restrict__ bias,
                                  const float* __restrict__ xp, int useGates)
{
    int idx = blockIdx.x * blockDim.x + threadIdx.x;
    if (idx >= B_ * H_) return;
    const int b = idx >> 9, j = idx & 511;
    const float* gr = g_gates + (size_t)b * G4H_;
    const float* xr = xp + ((size_t)b * L_ + t) * G4H_;
    float vi = xr[j] + bias[j];
    float vf = xr[H_ + j] + bias[H_ + j];
    float vg = xr[2 * H_ + j] + bias[2 * H_ + j];
    float vo = xr[3 * H_ + j] + bias[3 * H_ + j];
    if (useGates) {
        vi += gr[j]; vf += gr[H_ + j]; vg += gr[2 * H_ + j]; vo += gr[3 * H_ + j];
    }
    const float ig = dsigmoid(vi);
    const float fg = dsigmoid(vf);
    const float gg = tanhf(vg);
    const float og = dsigmoid(vo);
    const float cn = fg * g_c[idx] + ig * gg;
    const float hn = og * tanhf(cn);
    g_c[idx] = cn;
    __nv_bfloat16 b0, b1;
    split2(hn, b0, b1);
    g_hs[idx] = b0; g_hs[HS_STRIDE + idx] = b1;
    if (layer == 0) {
        const size_t o = ((size_t)b * L_ + t) * H_ + j;
        g_h1s[o] = b0; g_h1s[H1S_STRIDE + o] = b1;
    } else {
        g_h[idx] = hn;
    }
}

// ---------------- fp32 SGEMM (tails; proven) ----------------
#define BM 128
#define BN 128
#define BK 8
#define TM 8
#define TN 8
__global__ __launch_bounds__(256, 2)
void sgemm_dual(const float* __restrict__ A1, int lda1,
                const float* __restrict__ B1, int ldb1,
                const float* __restrict__ bias,
                const float* __restrict__ aux, int ldaux,
                float* __restrict__ C, int ldc, int K, int epi)
{
    __shared__ __align__(16) float As[2][BK][BM + 4];
    __shared__ __align__(16) float Bs[2][BK][BN + 4];
    const int tid = threadIdx.x, tx = tid & 15, ty = tid >> 4;
    const int rowBase = blockIdx.y * BM, colBase = blockIdx.x * BN;
    const int lr = tid >> 1, lk = (tid & 1) * 4;
    float acc[TM][TN];
#pragma unroll
    for (int i = 0; i < TM; i++)
#pragma unroll
        for (int j = 0; j < TN; j++) acc[i][j] = 0.f;
    const int ntiles = K / BK;
    {
        float4 av = *(const float4*)(A1 + (size_t)(rowBase + lr) * lda1 + lk);
        float4 bv = *(const float4*)(B1 + (size_t)(colBase + lr) * ldb1 + lk);
        As[0][lk + 0][lr] = av.x; As[0][lk + 1][lr] = av.y;
        As[0][lk + 2][lr] = av.z; As[0][lk + 3][lr] = av.w;
        Bs[0][lk + 0][lr] = bv.x; Bs[0][lk + 1][lr] = bv.y;
        Bs[0][lk + 2][lr] = bv.z; Bs[0][lk + 3][lr] = bv.w;
    }
    __syncthreads();
    for (int kt = 0; kt < ntiles; kt++) {
        const int buf = kt & 1;
        float4 av2, bv2;
        const bool hasNext = (kt + 1 < ntiles);
        if (hasNext) {
            const int k0 = (kt + 1) * BK;
            av2 = *(const float4*)(A1 + (size_t)(rowBase + lr) * lda1 + k0 + lk);
            bv2 = *(const float4*)(B1 + (size_t)(colBase + lr) * ldb1 + k0 + lk);
        }
#pragma unroll
        for (int kk = 0; kk < BK; kk++) {
            float4 a0 = *(const float4*)&As[buf][kk][ty * TM];
            float4 a1 = *(const float4*)&As[buf][kk][ty * TM + 4];
            float4 b0 = *(const float4*)&Bs[buf][kk][tx * TN];
            float4 b1 = *(const float4*)&Bs[buf][kk][tx * TN + 4];
            float a[TM] = {a0.x, a0.y, a0.z, a0.w, a1.x, a1.y, a1.z, a1.w};
            float b[TN] = {b0.x, b0.y, b0.z, b0.w, b1.x, b1.y, b1.z, b1.w};
#pragma unroll
            for (int i = 0; i < TM; i++)
#pragma unroll
                for (int j = 0; j < TN; j++)
                    acc[i][j] = fmaf(a[i], b[j], acc[i][j]);
        }
        if (hasNext) {
            const int nb = buf ^ 1;
            As[nb][lk + 0][lr] = av2.x; As[nb][lk + 1][lr] = av2.y;
            As[nb][lk + 2][lr] = av2.z; As[nb][lk + 3][lr] = av2.w;
            Bs[nb][lk + 0][lr] = bv2.x; Bs[nb][lk + 1][lr] = bv2.y;
            Bs[nb][lk + 2][lr] = bv2.z; Bs[nb][lk + 3][lr] = bv2.w;
            __syncthreads();
        }
    }
#pragma unroll
    for (int i = 0; i < TM; i++) {
        const int r = rowBase + ty * TM + i;
#pragma unroll
        for (int j = 0; j < TN; j++) {
            const int cidx = colBase + tx * TN + j;
            float v = acc[i][j] + bias[cidx];
            if (epi == 1) v = v > 0.f ? v : 0.f;
            else if (epi == 2) v = aux[(size_t)r * ldaux + cidx] * (1.f / (1.f + expf(-v)));
            C[(size_t)r * ldc + cidx] = v;
        }
    }
}

__global__ void topk_mask_kernel(const float* __restrict__ out_sub, const float* __restrict__ y)
{
    const int warp = (blockIdx.x * blockDim.x + threadIdx.x) >> 5;
    const int lane = threadIdx.x & 31;
    if (warp >= B_) return;
    const float* row = out_sub + (size_t)warp * C_;
    float p = 0.f;
#pragma unroll
    for (int k = 0; k < 8; k++) p += row[lane * 8 + k];
    unsigned selmask = 0;
    float v = p;
#pragma unroll
    for (int it = 0; it < 8; it++) {
        float m = v; int mi = lane;
#pragma unroll
        for (int off = 16; off; off >>= 1) {
            const float ov = __shfl_xor_sync(0xffffffffu, m, off);
            const int   oi = __shfl_xor_sync(0xffffffffu, mi, off);
            if (ov > m || (ov == m && oi < mi)) { m = ov; mi = oi; }
        }
        selmask |= 1u << mi;
        if (lane == mi) v = -INFINITY;
    }
    const float sel = ((selmask >> lane) & 1u) ? 1.f : 0.f;
    const size_t base = (size_t)warp * FM_ + 2 * lane;
    g_immm[base]     = y[base]     * sel;
    g_immm[base + 1] = y[base + 1] * sel;
}

__global__ void cat_kernel(const float* __restrict__ out_sub, const float* __restrict__ out_mm)
{
    int idx = blockIdx.x * blockDim.x + threadIdx.x;
    if (idx >= B_ * 2 * C_) return;
    const int b = idx >> 9, j = idx & 511;
    g_cat[idx] = (j < C_) ? out_sub[(size_t)b * C_ + j] : out_mm[(size_t)b * C_ + (j - C_)];
}

// ---------------- host ----------------
static inline void gemm32(const float* A, int lda, const float* Bw, int ldb,
                          const float* bias, const float* aux, int ldaux,
                          float* C, int ldc, int M, int N, int K, int epi)
{
    dim3 grid(N / BN, M / BM);
    sgemm_dual<<<grid, 256>>>(A, lda, Bw, ldb, bias, aux, ldaux, C, ldc, K, epi);
}

extern "C" void kernel_launch(void* const* d_in, const int* in_sizes, int n_in,
                              void* d_out, int out_size)
{
    const float* x    = (const float*)d_in[0];
    const float* y    = (const float*)d_in[1];
    const float* Wih0 = (const float*)d_in[2];
    const float* Whh0 = (const float*)d_in[3];
    const float* bih0 = (const float*)d_in[4];
    const float* bhh0 = (const float*)d_in[5];
    const float* Wih1 = (const float*)d_in[6];
    const float* Whh1 = (const float*)d_in[7];
    const float* bih1 = (const float*)d_in[8];
    const float* bhh1 = (const float*)d_in[9];
    const float* decW = (const float*)d_in[10];
    const float* decb = (const float*)d_in[11];
    const float* mmW1 = (const float*)d_in[12];
    const float* mmb1 = (const float*)d_in[13];
    const float* mmW2 = (const float*)d_in[14];
    const float* mmb2 = (const float*)d_in[15];
    const float* mmW3 = (const float*)d_in[16];
    const float* mmb3 = (const float*)d_in[17];
    const float* attW = (const float*)d_in[18];
    const float* attb = (const float*)d_in[19];
    const float* fuW1 = (const float*)d_in[20];
    const float* fub1 = (const float*)d_in[21];
    const float* fuW2 = (const float*)d_in[22];
    const float* fub2 = (const float*)d_in[23];
    const float* fuW3 = (const float*)d_in[24];
    const float* fub3 = (const float*)d_in[25];
    (void)in_sizes; (void)n_in; (void)out_size;

    float* out     = (float*)d_out;
    float* out_sub = out;
    float* out_mm  = out + (size_t)B_ * C_;
    float* out_fu  = out + (size_t)2 * B_ * C_;

    float *gates, *xp0, *xp1, *h, *bs0, *bs1, *immm, *t1, *t2, *cat, *fused;
    __nv_bfloat16 *xs, *h1s, *hs, *wi0, *wh0, *wi1, *wh1;
    cudaGetSymbolAddress((void**)&gates, g_gates);
    cudaGetSymbolAddress((void**)&xp0,   g_xp0);
    cudaGetSymbolAddress((void**)&xp1,   g_xp1);
    cudaGetSymbolAddress((void**)&h,     g_h);
    cudaGetSymbolAddress((void**)&bs0,   g_bias0);
    cudaGetSymbolAddress((void**)&bs1,   g_bias1);
    cudaGetSymbolAddress((void**)&immm,  g_immm);
    cudaGetSymbolAddress((void**)&t1,    g_t1);
    cudaGetSymbolAddress((void**)&t2,    g_t2);
    cudaGetSymbolAddress((void**)&cat,   g_cat);
    cudaGetSymbolAddress((void**)&fused, g_fused);
    cudaGetSymbolAddress((void**)&xs,    g_xs);
    cudaGetSymbolAddress((void**)&h1s,   g_h1s);
    cudaGetSymbolAddress((void**)&hs,    g_hs);
    cudaGetSymbolAddress((void**)&wi0,   g_Wi0);
    cudaGetSymbolAddress((void**)&wh0,   g_Wh0);
    cudaGetSymbolAddress((void**)&wi1,   g_Wi1);
    cudaGetSymbolAddress((void**)&wh1,   g_Wh1);

    const int hcBlocks = (B_ * H_ + 255) / 256;
    prep_bias_kernel<<<(G4H_ + 255) / 256, 256>>>(bih0, bhh0, bih1, bhh1);
    split_x_kernel<<<(int)(XS_STRIDE / 256), 256>>>(x);
    split_w_kernel<<<(G4H_ * FEAT_ + 255) / 256, 256>>>(Wih0, wi0, (size_t)G4H_ * FEAT_, G4H_ * FEAT_);
    split_w_kernel<<<(G4H_ * H_ + 255) / 256, 256>>>(Whh0, wh0, (size_t)G4H_ * H_, G4H_ * H_);
    split_w_kernel<<<(G4H_ * H_ + 255) / 256, 256>>>(Wih1, wi1, (size_t)G4H_ * H_, G4H_ * H_);
    split_w_kernel<<<(G4H_ * H_ + 255) / 256, 256>>>(Whh1, wh1, (size_t)G4H_ * H_, G4H_ * H_);

    const dim3 sgrid(G4H_ / 128, B_ / 128);          // per-step recurrent GEMM
    const dim3 bgrid(G4H_ / 128, (B_ * L_) / 128);   // big input-projection GEMM

    // ---- layer 0 ----
    {
        GemmArgs pre;                                 // xp0 = x @ Wih0^T (3 split products)
        pre.sA0 = FEAT_; pre.sB0 = FEAT_; pre.sA1 = 0; pre.sB1 = 0;
        for (int l = 0; l < 2; l++) {
            pre.A0[l] = xs + (size_t)l * XS_STRIDE;
            pre.B0[l] = wi0 + (size_t)l * G4H_ * FEAT_;
            pre.A1[l] = nullptr; pre.B1[l] = nullptr;
        }
        pre.Cout = xp0;
        lstm_gemm<4, 4, 12><<<bgrid, 256>>>(pre);
    }
    zero_state_kernel<<<hcBlocks, 256>>>();
    {
        GemmArgs a;                                   // recurrent part: h @ Whh0^T
        a.sA0 = 0; a.sB0 = 0; a.sA1 = H_; a.sB1 = H_;
        for (int l = 0; l < 2; l++) {
            a.A0[l] = nullptr; a.B0[l] = nullptr;
            a.A1[l] = hs + (size_t)l * HS_STRIDE;
            a.B1[l] = wh0 + (size_t)l * G4H_ * H_;
        }
        a.Cout = gates;
        for (int t = 0; t < L_; t++) {
            if (t > 0) lstm_gemm<16, 0, 48><<<sgrid, 256>>>(a);
            lstm_cell2_kernel<<<hcBlocks, 256>>>(t, 0, bs0, xp0, t > 0);
        }
    }
    // ---- layer 1 ----
    {
        GemmArgs pre;                                 // xp1 = h1 @ Wih1^T
        pre.sA0 = H_; pre.sB0 = H_; pre.sA1 = 0; pre.sB1 = 0;
        for (int l = 0; l < 2; l++) {
            pre.A0[l] = h1s + (size_t)l * H1S_STRIDE;
            pre.B0[l] = wi1 + (size_t)l * G4H_ * H_;
            pre.A1[l] = nullptr; pre.B1[l] = nullptr;
        }
        pre.Cout = xp1;
        lstm_gemm<16, 16, 48><<<bgrid, 256>>>(pre);
    }
    zero_state_kernel<<<hcBlocks, 256>>>();
    {
        GemmArgs a;                                   // recurrent part: h @ Whh1^T
        a.sA0 = 0; a.sB0 = 0; a.sA1 = H_; a.sB1 = H_;
        for (int l = 0; l < 2; l++) {
            a.A0[l] = nullptr; a.B0[l] = nullptr;
            a.A1[l] = hs + (size_t)l * HS_STRIDE;
            a.B1[l] = wh1 + (size_t)l * G4H_ * H_;
        }
        a.Cout = gates;
        for (int t = 0; t < L_; t++) {
            if (t > 0) lstm_gemm<16, 0, 48><<<sgrid, 256>>>(a);
            lstm_cell2_kernel<<<hcBlocks, 256>>>(t, 1, bs1, xp1, t > 0);
        }
    }

    // ---- tails (fp32, proven) ----
    gemm32(h, H_, decW, H_, decb, nullptr, 0, out_sub, C_, B_, C_, H_, 0);
    topk_mask_kernel<<<(B_ * 32 + 255) / 256, 256>>>(out_sub, y);
    gemm32(immm, FM_, mmW1, FM_, mmb1, nullptr, 0, t1, H_, B_, H_, FM_, 1);
    gemm32(t1, H_, mmW2, H_, mmb2, nullptr, 0, t2, H_, B_, H_, H_, 1);
    gemm32(t2, H_, mmW3, H_, mmb3, nullptr, 0, out_mm, C_, B_, C_, H_, 0);
    cat_kernel<<<(B_ * 2 * C_ + 255) / 256, 256>>>(out_sub, out_mm);
    gemm32(cat, 2 * C_, attW, 2 * C_, attb, cat, 2 * C_, fused, 2 * C_, B_, 2 * C_, 2 * C_, 2);
    gemm32(fused, 2 * C_, fuW1, 2 * C_, fub1, nullptr, 0, t1, H_, B_, H_, 2 * C_, 1);
    gemm32(t1, H_, fuW2, H_, fub2, nullptr, 0, t2, H_, B_, H_, H_, 1);
    gemm32(t2, H_, fuW3, H_, fub3, nullptr, 0, out_fu, C_, B_, C_, H_, 0);
}